// round 3
// baseline (speedup 1.0000x reference)
#include <cuda_runtime.h>
#include <math.h>

// Problem shapes (fixed by setup_inputs)
#define S_DIM 1024
#define B_DIM 2
#define D_DIM 1024
#define LP1   4
#define H_DIM 16
#define HD    64
#define BHD   (B_DIM * H_DIM)              // 32
#define ROWS  (B_DIM * D_DIM)              // 2048
#define M_X   (S_DIM * B_DIM)              // 2048
#define M_LO  ((LP1 - 1) * S_DIM * B_DIM)  // 6144

typedef unsigned long long u64;

// Packed f32x2 helpers (FFMA2 — 2 FMAs per issued instruction on sm_103a)
__device__ __forceinline__ u64 ffma2(u64 a, u64 b, u64 c) {
    u64 d;
    asm("fma.rn.f32x2 %0, %1, %2, %3;" : "=l"(d) : "l"(a), "l"(b), "l"(c));
    return d;
}
__device__ __forceinline__ u64 pack2(float x, float y) {
    u64 d;
    asm("mov.b64 %0, {%1, %2};" : "=l"(d) : "f"(x), "f"(y));
    return d;
}
__device__ __forceinline__ void unpack2(u64 v, float& lo, float& hi) {
    asm("mov.b64 {%0, %1}, %2;" : "=f"(lo), "=f"(hi) : "l"(v));
}

// Scratch (static device arrays — no runtime allocation)
__device__ float g_Q[(size_t)M_X * D_DIM];
__device__ float g_K[(size_t)LP1 * M_X * D_DIM];
__device__ float g_V[(size_t)LP1 * M_X * D_DIM];
__device__ float g_C[(size_t)M_X * D_DIM];

// ---------------------------------------------------------------------------
// Batched SGEMM via f32x2:  C_z[M,N] = A[M,K] @ W_z[N,K]^T + bias_z.
// 128x128 block, BK=8, 256 threads, 8x8 per-thread tile (stored as 8x4 pairs).
// ---------------------------------------------------------------------------
#define MAXB 3
struct GemmOuts {
    const float* W[MAXB];
    const float* bias[MAXB];
    float*       C[MAXB];
};

__global__ void __launch_bounds__(256) gemm_tn(const float* __restrict__ A,
                                               GemmOuts outs) {
    const int K = D_DIM;
    const int N = D_DIM;
    const float* __restrict__ W    = outs.W[blockIdx.z];
    const float* __restrict__ bias = outs.bias[blockIdx.z];
    float* __restrict__ Cout       = outs.C[blockIdx.z];

    __shared__ __align__(16) float As[8][128];
    __shared__ __align__(16) float Ws[8][128];

    const int bm  = blockIdx.y * 128;
    const int bn  = blockIdx.x * 128;
    const int tid = threadIdx.x;

    const int arow  = tid >> 1;
    const int acol4 = (tid & 1) * 4;

    const float* Ag = A + (size_t)(bm + arow) * K + acol4;
    const float* Wg = W + (size_t)(bn + arow) * K + acol4;

    const int tx = tid & 15;   // n-dir
    const int ty = tid >> 4;   // m-dir

    u64 acc2[8][4];            // 8 rows x 4 column-pairs
#pragma unroll
    for (int i = 0; i < 8; ++i)
#pragma unroll
        for (int j = 0; j < 4; ++j) acc2[i][j] = 0ULL;

    float4 av = *(const float4*)(Ag);
    float4 wv = *(const float4*)(Wg);

    for (int k0 = 0; k0 < K; k0 += 8) {
        __syncthreads();
        As[acol4 + 0][arow] = av.x;
        As[acol4 + 1][arow] = av.y;
        As[acol4 + 2][arow] = av.z;
        As[acol4 + 3][arow] = av.w;
        Ws[acol4 + 0][arow] = wv.x;
        Ws[acol4 + 1][arow] = wv.y;
        Ws[acol4 + 2][arow] = wv.z;
        Ws[acol4 + 3][arow] = wv.w;
        __syncthreads();

        if (k0 + 8 < K) {
            av = *(const float4*)(Ag + k0 + 8);
            wv = *(const float4*)(Wg + k0 + 8);
        }

#pragma unroll
        for (int kk = 0; kk < 8; ++kk) {
            float a[8];
            *(float4*)(a + 0) = *(const float4*)&As[kk][ty * 8 + 0];
            *(float4*)(a + 4) = *(const float4*)&As[kk][ty * 8 + 4];
            const ulonglong2* wrow = (const ulonglong2*)&Ws[kk][tx * 8];
            ulonglong2 wv0 = wrow[0];
            ulonglong2 wv1 = wrow[1];
            u64 w2[4] = {wv0.x, wv0.y, wv1.x, wv1.y};
#pragma unroll
            for (int i = 0; i < 8; ++i) {
                u64 a2 = pack2(a[i], a[i]);
#pragma unroll
                for (int j = 0; j < 4; ++j)
                    acc2[i][j] = ffma2(a2, w2[j], acc2[i][j]);
            }
        }
    }

    // epilogue: unpack, add bias, store
    float4 b0 = *(const float4*)(bias + bn + tx * 8 + 0);
    float4 b1 = *(const float4*)(bias + bn + tx * 8 + 4);
#pragma unroll
    for (int i = 0; i < 8; ++i) {
        const int row = bm + ty * 8 + i;
        float* crow = Cout + (size_t)row * N + bn + tx * 8;
        float o[8];
#pragma unroll
        for (int j = 0; j < 4; ++j) unpack2(acc2[i][j], o[2 * j], o[2 * j + 1]);
        float4 s0, s1;
        s0.x = o[0] + b0.x; s0.y = o[1] + b0.y; s0.z = o[2] + b0.z; s0.w = o[3] + b0.w;
        s1.x = o[4] + b1.x; s1.y = o[5] + b1.y; s1.z = o[6] + b1.z; s1.w = o[7] + b1.w;
        *(float4*)(crow + 0) = s0;
        *(float4*)(crow + 4) = s1;
    }
}

// ---------------------------------------------------------------------------
// Layer-wise attention with f32x2 inner loops.
// One thread per query row; K/V tiles (64 keys x 64 dim) in shared;
// online softmax; layer-weighted accumulation into g_C.
// ---------------------------------------------------------------------------
__global__ void __launch_bounds__(128) attn_kernel(
    const float* __restrict__ Q, const float* __restrict__ Kg,
    const float* __restrict__ Vg, const float* __restrict__ lw_in,
    float* __restrict__ Cc) {
    const int bh   = blockIdx.x;
    const int t    = threadIdx.x;
    const int srow = blockIdx.y * 128 + t;

    __shared__ __align__(16) float Ks[64][HD];
    __shared__ __align__(16) float Vs[64][HD];

    // q row -> register pairs
    u64 q2[HD / 2];
    {
        const ulonglong2* qp =
            (const ulonglong2*)(Q + (size_t)srow * ROWS + bh * HD);
#pragma unroll
        for (int i = 0; i < HD / 4; ++i) {
            ulonglong2 v = qp[i];
            q2[2 * i + 0] = v.x;
            q2[2 * i + 1] = v.y;
        }
    }

    // softmax over layer weights
    float lw[LP1];
    {
        float l0 = lw_in[0], l1 = lw_in[1], l2 = lw_in[2], l3 = lw_in[3];
        float mx = fmaxf(fmaxf(l0, l1), fmaxf(l2, l3));
        float e0 = expf(l0 - mx), e1 = expf(l1 - mx);
        float e2 = expf(l2 - mx), e3 = expf(l3 - mx);
        float inv = 1.f / (e0 + e1 + e2 + e3);
        lw[0] = e0 * inv; lw[1] = e1 * inv; lw[2] = e2 * inv; lw[3] = e3 * inv;
    }

    const float sc = 0.125f * 1.44269504088896340736f;  // hd^-0.5 * log2(e)

    for (int l = 0; l < LP1; ++l) {
        const float* Kl = Kg + (size_t)l * M_X * D_DIM;
        const float* Vl = Vg + (size_t)l * M_X * D_DIM;

        float m = -1e30f, ssum = 0.f;
        u64 acc2[HD / 2];
#pragma unroll
        for (int d = 0; d < HD / 2; ++d) acc2[d] = 0ULL;

        for (int kt = 0; kt < S_DIM; kt += 64) {
            __syncthreads();
#pragma unroll
            for (int i = 0; i < 8; ++i) {
                int idx = i * 128 + t;
                int j   = idx >> 4;
                int dp  = (idx & 15) << 2;
                size_t goff = (size_t)(kt + j) * ROWS + bh * HD + dp;
                *(float4*)&Ks[j][dp] = *(const float4*)(Kl + goff);
                *(float4*)&Vs[j][dp] = *(const float4*)(Vl + goff);
            }
            __syncthreads();

            for (int j = 0; j < 64; ++j) {
                // q . k  (paired along head-dim, 2 accumulators)
                u64 s2a = 0ULL, s2b = 0ULL;
                const ulonglong2* kr = (const ulonglong2*)&Ks[j][0];
#pragma unroll
                for (int c = 0; c < HD / 4; ++c) {
                    ulonglong2 kv = kr[c];
                    s2a = ffma2(q2[2 * c + 0], kv.x, s2a);
                    s2b = ffma2(q2[2 * c + 1], kv.y, s2b);
                }
                float alo, ahi, blo, bhi;
                unpack2(s2a, alo, ahi);
                unpack2(s2b, blo, bhi);
                float s = ((alo + ahi) + (blo + bhi)) * sc;

                const ulonglong2* vr = (const ulonglong2*)&Vs[j][0];
                if (s <= m) {                     // common path
                    float p = exp2f(s - m);
                    ssum += p;
                    u64 p2 = pack2(p, p);
#pragma unroll
                    for (int c = 0; c < HD / 4; ++c) {
                        ulonglong2 vv = vr[c];
                        acc2[2 * c + 0] = ffma2(p2, vv.x, acc2[2 * c + 0]);
                        acc2[2 * c + 1] = ffma2(p2, vv.y, acc2[2 * c + 1]);
                    }
                } else {                          // rare: new max
                    float r = exp2f(m - s);
                    ssum = ssum * r + 1.f;
                    u64 r2 = pack2(r, r);
#pragma unroll
                    for (int c = 0; c < HD / 4; ++c) {
                        ulonglong2 vv = vr[c];
                        acc2[2 * c + 0] = ffma2(acc2[2 * c + 0], r2, vv.x);
                        acc2[2 * c + 1] = ffma2(acc2[2 * c + 1], r2, vv.y);
                    }
                    m = s;
                }
            }
        }

        // layer-weighted accumulate into combined buffer
        const float w = lw[l] / ssum;
        float* cp = Cc + (size_t)srow * ROWS + bh * HD;
        if (l == 0) {
#pragma unroll
            for (int d = 0; d < HD / 2; ++d) {
                float lo, hi;
                unpack2(acc2[d], lo, hi);
                cp[2 * d + 0] = w * lo;
                cp[2 * d + 1] = w * hi;
            }
        } else {
#pragma unroll
            for (int d = 0; d < HD / 2; ++d) {
                float lo, hi;
                unpack2(acc2[d], lo, hi);
                cp[2 * d + 0] += w * lo;
                cp[2 * d + 1] += w * hi;
            }
        }
    }
}

// ---------------------------------------------------------------------------
extern "C" void kernel_launch(void* const* d_in, const int* in_sizes, int n_in,
                              void* d_out, int out_size) {
    const float* x  = (const float*)d_in[0];
    const float* lo = (const float*)d_in[1];
    const float* Wq = (const float*)d_in[2];
    const float* bq = (const float*)d_in[3];
    const float* Wk = (const float*)d_in[4];
    const float* bk = (const float*)d_in[5];
    const float* Wv = (const float*)d_in[6];
    const float* bv = (const float*)d_in[7];
    const float* Wo = (const float*)d_in[8];
    const float* bo = (const float*)d_in[9];
    const float* lw = (const float*)d_in[10];
    float* out = (float*)d_out;

    float *Qp, *Kp, *Vp, *Cp;
    cudaGetSymbolAddress((void**)&Qp, g_Q);
    cudaGetSymbolAddress((void**)&Kp, g_K);
    cudaGetSymbolAddress((void**)&Vp, g_V);
    cudaGetSymbolAddress((void**)&Cp, g_C);

    const dim3 blk(256);

    // 1) x -> Q, K[0], V[0]
    {
        GemmOuts o;
        o.W[0] = Wq; o.bias[0] = bq; o.C[0] = Qp;
        o.W[1] = Wk; o.bias[1] = bk; o.C[1] = Kp;
        o.W[2] = Wv; o.bias[2] = bv; o.C[2] = Vp;
        dim3 grid(D_DIM / 128, M_X / 128, 3);
        gemm_tn<<<grid, blk>>>(x, o);
    }
    // 2) layer_outputs -> K[1..3], V[1..3]
    {
        GemmOuts o;
        o.W[0] = Wk; o.bias[0] = bk; o.C[0] = Kp + (size_t)M_X * D_DIM;
        o.W[1] = Wv; o.bias[1] = bv; o.C[1] = Vp + (size_t)M_X * D_DIM;
        o.W[2] = Wk; o.bias[2] = bk; o.C[2] = Kp + (size_t)M_X * D_DIM;
        dim3 grid(D_DIM / 128, M_LO / 128, 2);
        gemm_tn<<<grid, blk>>>(lo, o);
    }
    // 3) attention -> combined
    attn_kernel<<<dim3(BHD, S_DIM / 128), 128>>>(Qp, Kp, Vp, lw, Cp);
    // 4) combined @ Wo^T + bo -> out
    {
        GemmOuts o;
        o.W[0] = Wo; o.bias[0] = bo; o.C[0] = out;
        o.W[1] = Wo; o.bias[1] = bo; o.C[1] = out;
        o.W[2] = Wo; o.bias[2] = bo; o.C[2] = out;
        dim3 grid(D_DIM / 128, M_X / 128, 1);
        gemm_tn<<<grid, blk>>>(Cp, o);
    }
}

// round 5
// speedup vs baseline: 1.7317x; 1.7317x over previous
#include <cuda_runtime.h>
#include <math.h>
#include <stdint.h>

// Problem shapes (fixed by setup_inputs)
#define S_DIM 1024
#define B_DIM 2
#define D_DIM 1024
#define LP1   4
#define H_DIM 16
#define HD    64
#define BHD   (B_DIM * H_DIM)              // 32
#define ROWS  (B_DIM * D_DIM)              // 2048
#define M_X   (S_DIM * B_DIM)              // 2048
#define M_LO  ((LP1 - 1) * S_DIM * B_DIM)  // 6144

// Scratch (static device arrays — no runtime allocation)
__device__ float g_Q[(size_t)M_X * D_DIM];
__device__ float g_K[(size_t)LP1 * M_X * D_DIM];
__device__ float g_V[(size_t)LP1 * M_X * D_DIM];
__device__ float g_C[(size_t)M_X * D_DIM];

// ---------------------------------------------------------------------------
// Helpers
// ---------------------------------------------------------------------------
__device__ __forceinline__ uint32_t smem_u32(const void* p) {
    uint32_t a;
    asm("{ .reg .u64 t; cvta.to.shared.u64 t, %1; cvt.u32.u64 %0, t; }"
        : "=r"(a) : "l"(p));
    return a;
}
// pack two fp32 -> bf16x2 (lo = a, hi = b)
__device__ __forceinline__ uint32_t cvt2bf(float a, float b) {
    uint32_t r;
    asm("cvt.rn.bf16x2.f32 %0, %1, %2;" : "=r"(r) : "f"(b), "f"(a));
    return r;
}
__device__ __forceinline__ float bflo(uint32_t p) { return __uint_as_float(p << 16); }
__device__ __forceinline__ float bfhi(uint32_t p) { return __uint_as_float(p & 0xffff0000u); }

__device__ __forceinline__ void ldmx4(uint32_t* r, uint32_t addr) {
    asm volatile("ldmatrix.sync.aligned.m8n8.x4.shared.b16 {%0,%1,%2,%3}, [%4];"
                 : "=r"(r[0]), "=r"(r[1]), "=r"(r[2]), "=r"(r[3]) : "r"(addr));
}
__device__ __forceinline__ void ldmx2(uint32_t* r, uint32_t addr) {
    asm volatile("ldmatrix.sync.aligned.m8n8.x2.shared.b16 {%0,%1}, [%2];"
                 : "=r"(r[0]), "=r"(r[1]) : "r"(addr));
}
__device__ __forceinline__ void mma_bf16(float* d, const uint32_t* a,
                                         const uint32_t* b) {
    asm volatile(
        "mma.sync.aligned.m16n8k16.row.col.f32.bf16.bf16.f32 "
        "{%0,%1,%2,%3}, {%4,%5,%6,%7}, {%8,%9}, {%0,%1,%2,%3};"
        : "+f"(d[0]), "+f"(d[1]), "+f"(d[2]), "+f"(d[3])
        : "r"(a[0]), "r"(a[1]), "r"(a[2]), "r"(a[3]), "r"(b[0]), "r"(b[1]));
}

// ---------------------------------------------------------------------------
// Tensor-core SGEMM via bf16 hi/lo split + mma.sync:
//   C_z[M,N] = A[M,K] @ W_z[N,K]^T + bias_z,   K = N = 1024.
// 128x128 CTA tile, 8 warps x (64x32), K-chunk 64.
// C = Ah*Wh + Ah*Wl + Al*Wh  (fp32 accum; Al*Wl dropped, ~2^-18 rel).
// ---------------------------------------------------------------------------
#define MAXB 3
struct GemmOuts {
    const float* W[MAXB];
    const float* bias[MAXB];
    float*       C[MAXB];
};

#define PADK 72                          // halves per smem row (64 + 8 pad)
#define TILE_HALVES (128 * PADK)         // one 128x64 bf16 tile
#define SMEM_BYTES (4 * TILE_HALVES * 2) // Ah, Al, Wh, Wl = 73728 B

__global__ void __launch_bounds__(256) gemm_mma(const float* __restrict__ A,
                                                GemmOuts outs) {
    extern __shared__ __align__(16) uint16_t sh[];
    uint16_t* Ah = sh;
    uint16_t* Al = sh + TILE_HALVES;
    uint16_t* Wh = sh + 2 * TILE_HALVES;
    uint16_t* Wl = sh + 3 * TILE_HALVES;

    const float* __restrict__ W    = outs.W[blockIdx.z];
    const float* __restrict__ bias = outs.bias[blockIdx.z];
    float* __restrict__ Cout       = outs.C[blockIdx.z];

    const int bm   = blockIdx.y * 128;
    const int bn   = blockIdx.x * 128;
    const int tid  = threadIdx.x;
    const int wid  = tid >> 5;
    const int lane = tid & 31;
    const int wm   = (wid >> 2) * 64;    // warp M offset in tile
    const int wn   = (wid & 3) * 32;     // warp N offset in tile

    const uint32_t sb = smem_u32(sh);

    float d[4][4][4];
#pragma unroll
    for (int mi = 0; mi < 4; ++mi)
#pragma unroll
        for (int ni = 0; ni < 4; ++ni)
#pragma unroll
            for (int e = 0; e < 4; ++e) d[mi][ni][e] = 0.f;

    for (int k0 = 0; k0 < D_DIM; k0 += 64) {
        // ---- load fp32, split to bf16 hi/lo, store to padded smem ----
#pragma unroll
        for (int i = 0; i < 8; ++i) {
            int idx = i * 256 + tid;         // 0..2047
            int row = idx >> 4;              // 0..127
            int c4  = (idx & 15) << 2;       // 0,4,..,60
            int ho  = row * PADK + c4;       // half-index (8B-aligned offset)
            {
                float4 v = *(const float4*)(A + (size_t)(bm + row) * D_DIM + k0 + c4);
                uint32_t h0 = cvt2bf(v.x, v.y), h1 = cvt2bf(v.z, v.w);
                uint32_t l0 = cvt2bf(v.x - bflo(h0), v.y - bfhi(h0));
                uint32_t l1 = cvt2bf(v.z - bflo(h1), v.w - bfhi(h1));
                *(uint2*)(Ah + ho) = make_uint2(h0, h1);
                *(uint2*)(Al + ho) = make_uint2(l0, l1);
            }
            {
                float4 v = *(const float4*)(W + (size_t)(bn + row) * D_DIM + k0 + c4);
                uint32_t h0 = cvt2bf(v.x, v.y), h1 = cvt2bf(v.z, v.w);
                uint32_t l0 = cvt2bf(v.x - bflo(h0), v.y - bfhi(h0));
                uint32_t l1 = cvt2bf(v.z - bflo(h1), v.w - bfhi(h1));
                *(uint2*)(Wh + ho) = make_uint2(h0, h1);
                *(uint2*)(Wl + ho) = make_uint2(l0, l1);
            }
        }
        __syncthreads();

        // ---- compute: 4 k16-steps x (4x4 tiles) x 3 split terms ----
#pragma unroll
        for (int ks = 0; ks < 4; ++ks) {
            const int k16 = ks * 16;
            uint32_t ah[4][4], al[4][4];
            {
                const int ar = lane & 15, ac = (lane >> 4) * 8;
#pragma unroll
                for (int mi = 0; mi < 4; ++mi) {
                    uint32_t off = (uint32_t)((wm + mi * 16 + ar) * PADK + k16 + ac) * 2;
                    ldmx4(ah[mi], sb + off);
                    ldmx4(al[mi], sb + TILE_HALVES * 2 + off);
                }
            }
            uint32_t bh[4][2], bl[4][2];
            {
                const int br = lane & 7, bc = ((lane >> 3) & 1) * 8;
#pragma unroll
                for (int ni = 0; ni < 4; ++ni) {
                    uint32_t off = (uint32_t)((wn + ni * 8 + br) * PADK + k16 + bc) * 2;
                    ldmx2(bh[ni], sb + TILE_HALVES * 4 + off);
                    ldmx2(bl[ni], sb + TILE_HALVES * 6 + off);
                }
            }
#pragma unroll
            for (int mi = 0; mi < 4; ++mi)
#pragma unroll
                for (int ni = 0; ni < 4; ++ni) {
                    mma_bf16(d[mi][ni], ah[mi], bh[ni]);
                    mma_bf16(d[mi][ni], ah[mi], bl[ni]);
                    mma_bf16(d[mi][ni], al[mi], bh[ni]);
                }
        }
        __syncthreads();
    }

    // ---- epilogue: d-frags + bias -> global ----
    const int qr = lane >> 2;          // 0..7
    const int qc = (lane & 3) * 2;     // 0,2,4,6
#pragma unroll
    for (int ni = 0; ni < 4; ++ni) {
        const int n0 = bn + wn + ni * 8 + qc;
        const float bx = bias[n0], by = bias[n0 + 1];
#pragma unroll
        for (int mi = 0; mi < 4; ++mi) {
            const int m0 = bm + wm + mi * 16 + qr;
            float2 o0 = make_float2(d[mi][ni][0] + bx, d[mi][ni][1] + by);
            float2 o1 = make_float2(d[mi][ni][2] + bx, d[mi][ni][3] + by);
            *(float2*)(Cout + (size_t)m0 * D_DIM + n0) = o0;
            *(float2*)(Cout + (size_t)(m0 + 8) * D_DIM + n0) = o1;
        }
    }
}

// ---------------------------------------------------------------------------
// Layer-wise attention (R2 scalar version — known good).
// ---------------------------------------------------------------------------
__global__ void __launch_bounds__(128) attn_kernel(
    const float* __restrict__ Q, const float* __restrict__ Kg,
    const float* __restrict__ Vg, const float* __restrict__ lw_in,
    float* __restrict__ Cc) {
    const int bh   = blockIdx.x;
    const int t    = threadIdx.x;
    const int srow = blockIdx.y * 128 + t;

    __shared__ float Ks[64][HD];
    __shared__ float Vs[64][HD];

    float q[HD];
    {
        const float4* qp = (const float4*)(Q + (size_t)srow * ROWS + bh * HD);
#pragma unroll
        for (int i = 0; i < HD / 4; ++i) ((float4*)q)[i] = qp[i];
    }

    float lw[LP1];
    {
        float l0 = lw_in[0], l1 = lw_in[1], l2 = lw_in[2], l3 = lw_in[3];
        float mx = fmaxf(fmaxf(l0, l1), fmaxf(l2, l3));
        float e0 = expf(l0 - mx), e1 = expf(l1 - mx);
        float e2 = expf(l2 - mx), e3 = expf(l3 - mx);
        float inv = 1.f / (e0 + e1 + e2 + e3);
        lw[0] = e0 * inv; lw[1] = e1 * inv; lw[2] = e2 * inv; lw[3] = e3 * inv;
    }

    const float sc = 0.125f * 1.44269504088896340736f;

    for (int l = 0; l < LP1; ++l) {
        const float* Kl = Kg + (size_t)l * M_X * D_DIM;
        const float* Vl = Vg + (size_t)l * M_X * D_DIM;

        float m = -1e30f, ssum = 0.f;
        float acc[HD];
#pragma unroll
        for (int d = 0; d < HD; ++d) acc[d] = 0.f;

        for (int kt = 0; kt < S_DIM; kt += 64) {
            __syncthreads();
#pragma unroll
            for (int i = 0; i < 8; ++i) {
                int idx = i * 128 + t;
                int j   = idx >> 4;
                int dp  = (idx & 15) << 2;
                size_t goff = (size_t)(kt + j) * ROWS + bh * HD + dp;
                *(float4*)&Ks[j][dp] = *(const float4*)(Kl + goff);
                *(float4*)&Vs[j][dp] = *(const float4*)(Vl + goff);
            }
            __syncthreads();

            for (int j = 0; j < 64; ++j) {
                float s0 = 0.f, s1 = 0.f, s2 = 0.f, s3 = 0.f;
#pragma unroll
                for (int dd = 0; dd < HD; dd += 4) {
                    s0 += q[dd + 0] * Ks[j][dd + 0];
                    s1 += q[dd + 1] * Ks[j][dd + 1];
                    s2 += q[dd + 2] * Ks[j][dd + 2];
                    s3 += q[dd + 3] * Ks[j][dd + 3];
                }
                float s = ((s0 + s1) + (s2 + s3)) * sc;
                if (s <= m) {
                    float p = exp2f(s - m);
                    ssum += p;
#pragma unroll
                    for (int dd = 0; dd < HD; ++dd) acc[dd] += p * Vs[j][dd];
                } else {
                    float r = exp2f(m - s);
                    ssum = ssum * r + 1.f;
#pragma unroll
                    for (int dd = 0; dd < HD; ++dd) acc[dd] = acc[dd] * r + Vs[j][dd];
                    m = s;
                }
            }
        }

        const float w = lw[l] / ssum;
        float* cp = Cc + (size_t)srow * ROWS + bh * HD;
        if (l == 0) {
#pragma unroll
            for (int dd = 0; dd < HD; dd += 4) {
                float4 o;
                o.x = w * acc[dd + 0]; o.y = w * acc[dd + 1];
                o.z = w * acc[dd + 2]; o.w = w * acc[dd + 3];
                *(float4*)(cp + dd) = o;
            }
        } else {
#pragma unroll
            for (int dd = 0; dd < HD; dd += 4) {
                float4 c = *(const float4*)(cp + dd);
                c.x += w * acc[dd + 0]; c.y += w * acc[dd + 1];
                c.z += w * acc[dd + 2]; c.w += w * acc[dd + 3];
                *(float4*)(cp + dd) = c;
            }
        }
    }
}

// ---------------------------------------------------------------------------
extern "C" void kernel_launch(void* const* d_in, const int* in_sizes, int n_in,
                              void* d_out, int out_size) {
    const float* x  = (const float*)d_in[0];
    const float* lo = (const float*)d_in[1];
    const float* Wq = (const float*)d_in[2];
    const float* bq = (const float*)d_in[3];
    const float* Wk = (const float*)d_in[4];
    const float* bk = (const float*)d_in[5];
    const float* Wv = (const float*)d_in[6];
    const float* bv = (const float*)d_in[7];
    const float* Wo = (const float*)d_in[8];
    const float* bo = (const float*)d_in[9];
    const float* lw = (const float*)d_in[10];
    float* out = (float*)d_out;

    float *Qp, *Kp, *Vp, *Cp;
    cudaGetSymbolAddress((void**)&Qp, g_Q);
    cudaGetSymbolAddress((void**)&Kp, g_K);
    cudaGetSymbolAddress((void**)&Vp, g_V);
    cudaGetSymbolAddress((void**)&Cp, g_C);

    cudaFuncSetAttribute(gemm_mma, cudaFuncAttributeMaxDynamicSharedMemorySize,
                         SMEM_BYTES);

    // 1) x -> Q, K[0], V[0]
    {
        GemmOuts o;
        o.W[0] = Wq; o.bias[0] = bq; o.C[0] = Qp;
        o.W[1] = Wk; o.bias[1] = bk; o.C[1] = Kp;
        o.W[2] = Wv; o.bias[2] = bv; o.C[2] = Vp;
        gemm_mma<<<dim3(8, M_X / 128, 3), 256, SMEM_BYTES>>>(x, o);
    }
    // 2) layer_outputs -> K[1..3], V[1..3]
    {
        GemmOuts o;
        o.W[0] = Wk; o.bias[0] = bk; o.C[0] = Kp + (size_t)M_X * D_DIM;
        o.W[1] = Wv; o.bias[1] = bv; o.C[1] = Vp + (size_t)M_X * D_DIM;
        o.W[2] = Wk; o.bias[2] = bk; o.C[2] = Kp + (size_t)M_X * D_DIM;
        gemm_mma<<<dim3(8, M_LO / 128, 2), 256, SMEM_BYTES>>>(lo, o);
    }
    // 3) attention -> combined
    attn_kernel<<<dim3(BHD, S_DIM / 128), 128>>>(Qp, Kp, Vp, lw, Cp);
    // 4) combined @ Wo^T + bo -> out
    {
        GemmOuts o;
        o.W[0] = Wo; o.bias[0] = bo; o.C[0] = out;
        o.W[1] = Wo; o.bias[1] = bo; o.C[1] = out;
        o.W[2] = Wo; o.bias[2] = bo; o.C[2] = out;
        gemm_mma<<<dim3(8, M_X / 128, 1), 256, SMEM_BYTES>>>(Cp, o);
    }
}

// round 6
// speedup vs baseline: 4.8356x; 2.7925x over previous
#include <cuda_runtime.h>
#include <math.h>
#include <stdint.h>

// Problem shapes (fixed by setup_inputs)
#define S_DIM 1024
#define B_DIM 2
#define D_DIM 1024
#define LP1   4
#define H_DIM 16
#define HD    64
#define BHD   (B_DIM * H_DIM)              // 32
#define ROWS  (B_DIM * D_DIM)              // 2048
#define M_X   (S_DIM * B_DIM)              // 2048
#define M_LO  ((LP1 - 1) * S_DIM * B_DIM)  // 6144

// Scratch (static device arrays — no runtime allocation)
__device__ float g_Q[(size_t)M_X * D_DIM];
__device__ float g_K[(size_t)LP1 * M_X * D_DIM];
__device__ float g_V[(size_t)LP1 * M_X * D_DIM];
__device__ float g_C[(size_t)M_X * D_DIM];

// ---------------------------------------------------------------------------
// Helpers
// ---------------------------------------------------------------------------
__device__ __forceinline__ uint32_t smem_u32(const void* p) {
    uint32_t a;
    asm("{ .reg .u64 t; cvta.to.shared.u64 t, %1; cvt.u32.u64 %0, t; }"
        : "=r"(a) : "l"(p));
    return a;
}
// pack two fp32 -> bf16x2 (lo = a, hi = b)
__device__ __forceinline__ uint32_t cvt2bf(float a, float b) {
    uint32_t r;
    asm("cvt.rn.bf16x2.f32 %0, %1, %2;" : "=r"(r) : "f"(b), "f"(a));
    return r;
}
__device__ __forceinline__ float bflo(uint32_t p) { return __uint_as_float(p << 16); }
__device__ __forceinline__ float bfhi(uint32_t p) { return __uint_as_float(p & 0xffff0000u); }

__device__ __forceinline__ void ldmx4(uint32_t* r, uint32_t addr) {
    asm volatile("ldmatrix.sync.aligned.m8n8.x4.shared.b16 {%0,%1,%2,%3}, [%4];"
                 : "=r"(r[0]), "=r"(r[1]), "=r"(r[2]), "=r"(r[3]) : "r"(addr));
}
__device__ __forceinline__ void ldmx4t(uint32_t* r, uint32_t addr) {
    asm volatile("ldmatrix.sync.aligned.m8n8.x4.trans.shared.b16 {%0,%1,%2,%3}, [%4];"
                 : "=r"(r[0]), "=r"(r[1]), "=r"(r[2]), "=r"(r[3]) : "r"(addr));
}
__device__ __forceinline__ void ldmx2(uint32_t* r, uint32_t addr) {
    asm volatile("ldmatrix.sync.aligned.m8n8.x2.shared.b16 {%0,%1}, [%2];"
                 : "=r"(r[0]), "=r"(r[1]) : "r"(addr));
}
__device__ __forceinline__ void mma_bf16(float* d, const uint32_t* a,
                                         const uint32_t* b) {
    asm volatile(
        "mma.sync.aligned.m16n8k16.row.col.f32.bf16.bf16.f32 "
        "{%0,%1,%2,%3}, {%4,%5,%6,%7}, {%8,%9}, {%0,%1,%2,%3};"
        : "+f"(d[0]), "+f"(d[1]), "+f"(d[2]), "+f"(d[3])
        : "r"(a[0]), "r"(a[1]), "r"(a[2]), "r"(a[3]), "r"(b[0]), "r"(b[1]));
}

// ---------------------------------------------------------------------------
// Pipelined tensor-core SGEMM (bf16 hi/lo split):
//   C_z[M,N] = A[M,K] @ W_z[N,K]^T + bias_z,   K = N = 1024.
// 128x128 CTA tile, 8 warps x (64x32), K-chunk 64, ping-pong smem +
// register prefetch of the next chunk.
// ---------------------------------------------------------------------------
#define MAXB 3
struct GemmOuts {
    const float* W[MAXB];
    const float* bias[MAXB];
    float*       C[MAXB];
};

#define PADK 72                           // halves per smem row (64 + 8 pad)
#define TILE_HALVES (128 * PADK)          // one 128x64 bf16 tile
#define GEMM_SMEM (8 * TILE_HALVES * 2)   // 2 buffers x (Ah,Al,Wh,Wl)

__device__ __forceinline__ void split_store(uint16_t* Th, uint16_t* Tl,
                                            int ho, float4 v) {
    uint32_t h0 = cvt2bf(v.x, v.y), h1 = cvt2bf(v.z, v.w);
    uint32_t l0 = cvt2bf(v.x - bflo(h0), v.y - bfhi(h0));
    uint32_t l1 = cvt2bf(v.z - bflo(h1), v.w - bfhi(h1));
    *(uint2*)(Th + ho) = make_uint2(h0, h1);
    *(uint2*)(Tl + ho) = make_uint2(l0, l1);
}

__global__ void __launch_bounds__(256) gemm_mma(const float* __restrict__ A,
                                                GemmOuts outs) {
    extern __shared__ __align__(16) uint16_t sh[];

    const float* __restrict__ W    = outs.W[blockIdx.z];
    const float* __restrict__ bias = outs.bias[blockIdx.z];
    float* __restrict__ Cout       = outs.C[blockIdx.z];

    const int bm   = blockIdx.y * 128;
    const int bn   = blockIdx.x * 128;
    const int tid  = threadIdx.x;
    const int wid  = tid >> 5;
    const int lane = tid & 31;
    const int wm   = (wid >> 2) * 64;
    const int wn   = (wid & 3) * 32;

    const uint32_t sb = smem_u32(sh);

    // per-thread load coordinates (8 float4 per tensor per chunk)
    int lrow[8], lc4[8];
#pragma unroll
    for (int i = 0; i < 8; ++i) {
        int idx = i * 256 + tid;
        lrow[i] = idx >> 4;
        lc4[i]  = (idx & 15) << 2;
    }

    float d[4][4][4];
#pragma unroll
    for (int mi = 0; mi < 4; ++mi)
#pragma unroll
        for (int ni = 0; ni < 4; ++ni)
#pragma unroll
            for (int e = 0; e < 4; ++e) d[mi][ni][e] = 0.f;

    float4 pa[8], pw[8];
    // prologue: chunk 0 -> regs -> smem buf 0
#pragma unroll
    for (int i = 0; i < 8; ++i) {
        pa[i] = *(const float4*)(A + (size_t)(bm + lrow[i]) * D_DIM + lc4[i]);
        pw[i] = *(const float4*)(W + (size_t)(bn + lrow[i]) * D_DIM + lc4[i]);
    }
    {
        uint16_t* base = sh;
#pragma unroll
        for (int i = 0; i < 8; ++i) {
            int ho = lrow[i] * PADK + lc4[i];
            split_store(base, base + TILE_HALVES, ho, pa[i]);
            split_store(base + 2 * TILE_HALVES, base + 3 * TILE_HALVES, ho, pw[i]);
        }
    }
    __syncthreads();

    for (int it = 0; it < 16; ++it) {
        if (it < 15) {
            const int k0 = (it + 1) * 64;
#pragma unroll
            for (int i = 0; i < 8; ++i) {
                pa[i] = *(const float4*)(A + (size_t)(bm + lrow[i]) * D_DIM + k0 + lc4[i]);
                pw[i] = *(const float4*)(W + (size_t)(bn + lrow[i]) * D_DIM + k0 + lc4[i]);
            }
        }

        // ---- compute chunk `it` from buffer it&1 ----
        const uint32_t bufb = sb + (uint32_t)((it & 1) * 4 * TILE_HALVES) * 2;
#pragma unroll
        for (int ks = 0; ks < 4; ++ks) {
            const int k16 = ks * 16;
            uint32_t ah[4][4], al[4][4];
            {
                const int ar = lane & 15, ac = (lane >> 4) * 8;
#pragma unroll
                for (int mi = 0; mi < 4; ++mi) {
                    uint32_t off = (uint32_t)((wm + mi * 16 + ar) * PADK + k16 + ac) * 2;
                    ldmx4(ah[mi], bufb + off);
                    ldmx4(al[mi], bufb + TILE_HALVES * 2 + off);
                }
            }
            uint32_t bh[4][2], bl[4][2];
            {
                const int br = lane & 7, bc = ((lane >> 3) & 1) * 8;
#pragma unroll
                for (int ni = 0; ni < 4; ++ni) {
                    uint32_t off = (uint32_t)((wn + ni * 8 + br) * PADK + k16 + bc) * 2;
                    ldmx2(bh[ni], bufb + TILE_HALVES * 4 + off);
                    ldmx2(bl[ni], bufb + TILE_HALVES * 6 + off);
                }
            }
#pragma unroll
            for (int mi = 0; mi < 4; ++mi)
#pragma unroll
                for (int ni = 0; ni < 4; ++ni) {
                    mma_bf16(d[mi][ni], ah[mi], bh[ni]);
                    mma_bf16(d[mi][ni], ah[mi], bl[ni]);
                    mma_bf16(d[mi][ni], al[mi], bh[ni]);
                }
        }

        if (it < 15) {
            uint16_t* base = sh + ((it + 1) & 1) * 4 * TILE_HALVES;
#pragma unroll
            for (int i = 0; i < 8; ++i) {
                int ho = lrow[i] * PADK + lc4[i];
                split_store(base, base + TILE_HALVES, ho, pa[i]);
                split_store(base + 2 * TILE_HALVES, base + 3 * TILE_HALVES, ho, pw[i]);
            }
            __syncthreads();
        }
    }

    // ---- epilogue ----
    const int qr = lane >> 2;
    const int qc = (lane & 3) * 2;
#pragma unroll
    for (int ni = 0; ni < 4; ++ni) {
        const int n0 = bn + wn + ni * 8 + qc;
        const float bx = bias[n0], by = bias[n0 + 1];
#pragma unroll
        for (int mi = 0; mi < 4; ++mi) {
            const int m0 = bm + wm + mi * 16 + qr;
            *(float2*)(Cout + (size_t)m0 * D_DIM + n0) =
                make_float2(d[mi][ni][0] + bx, d[mi][ni][1] + by);
            *(float2*)(Cout + (size_t)(m0 + 8) * D_DIM + n0) =
                make_float2(d[mi][ni][2] + bx, d[mi][ni][3] + by);
        }
    }
}

// ---------------------------------------------------------------------------
// Tensor-core flash attention (bf16 hi/lo split, online softmax).
// Grid (BHD, 8): one CTA = one (bh, 128-q-row tile), all 4 layers.
// 8 warps x 16 q-rows. K/V chunks of 128 keys staged split in smem.
// ---------------------------------------------------------------------------
#define APAD PADK
#define ATILE (128 * APAD)          // halves per K/V tile
#define ATTN_SMEM (4 * ATILE * 2)   // Kh, Kl, Vh, Vl

__global__ void __launch_bounds__(256) attn_mma(
    const float* __restrict__ Q, const float* __restrict__ Kg,
    const float* __restrict__ Vg, const float* __restrict__ lw_in,
    float* __restrict__ Cc) {
    extern __shared__ __align__(16) uint16_t ash[];
    uint16_t* Kh = ash;
    uint16_t* Kl = ash + ATILE;
    uint16_t* Vh = ash + 2 * ATILE;
    uint16_t* Vl = ash + 3 * ATILE;
    const uint32_t sb = smem_u32(ash);

    const int bh    = blockIdx.x;
    const int qbase = blockIdx.y * 128;
    const int tid   = threadIdx.x;
    const int wid   = tid >> 5;
    const int lane  = tid & 31;
    const int wq    = wid * 16;
    const int r     = lane >> 2;
    const int c     = (lane & 3) * 2;

    // per-thread load coordinates for K/V chunk staging
    int lrow[8], lc4[8];
#pragma unroll
    for (int i = 0; i < 8; ++i) {
        int idx = i * 256 + tid;
        lrow[i] = idx >> 4;
        lc4[i]  = (idx & 15) << 2;
    }

    // ---- Q fragments (scaled by hd^-0.5 * log2e), hi/lo split ----
    const float qsc = 0.125f * 1.44269504088896340736f;
    uint32_t qh[4][4], ql[4][4];
#pragma unroll
    for (int s = 0; s < 4; ++s)
#pragma unroll
        for (int half = 0; half < 2; ++half)
#pragma unroll
            for (int rr = 0; rr < 2; ++rr) {
                const int row = qbase + wq + r + rr * 8;
                const int col = bh * HD + s * 16 + c + half * 8;
                float2 v = *(const float2*)(Q + (size_t)row * ROWS + col);
                float x = v.x * qsc, y = v.y * qsc;
                uint32_t h  = cvt2bf(x, y);
                uint32_t lo = cvt2bf(x - bflo(h), y - bfhi(h));
                qh[s][rr + half * 2] = h;
                ql[s][rr + half * 2] = lo;
            }

    // softmax over layer weights
    float lw[LP1];
    {
        float l0 = lw_in[0], l1 = lw_in[1], l2 = lw_in[2], l3 = lw_in[3];
        float mx = fmaxf(fmaxf(l0, l1), fmaxf(l2, l3));
        float e0 = expf(l0 - mx), e1 = expf(l1 - mx);
        float e2 = expf(l2 - mx), e3 = expf(l3 - mx);
        float inv = 1.f / (e0 + e1 + e2 + e3);
        lw[0] = e0 * inv; lw[1] = e1 * inv; lw[2] = e2 * inv; lw[3] = e3 * inv;
    }

    for (int l = 0; l < LP1; ++l) {
        const float* Kbase = Kg + (size_t)l * M_X * D_DIM;
        const float* Vbase = Vg + (size_t)l * M_X * D_DIM;

        float m0 = -1e30f, m1 = -1e30f, sum0 = 0.f, sum1 = 0.f;
        float o[8][4];
#pragma unroll
        for (int j = 0; j < 8; ++j)
#pragma unroll
            for (int e = 0; e < 4; ++e) o[j][e] = 0.f;

        for (int kt = 0; kt < 8; ++kt) {
            __syncthreads();
            // stage K/V chunk (128 keys x 64 hd), split bf16
#pragma unroll
            for (int i = 0; i < 8; ++i) {
                const size_t goff =
                    (size_t)(kt * 128 + lrow[i]) * ROWS + bh * HD + lc4[i];
                const int ho = lrow[i] * APAD + lc4[i];
                split_store(Kh, Kl, ho, *(const float4*)(Kbase + goff));
                split_store(Vh, Vl, ho, *(const float4*)(Vbase + goff));
            }
            __syncthreads();

            // ---- QK: S[16 x 128] per warp ----
            float sv[16][4];
#pragma unroll
            for (int nt2 = 0; nt2 < 8; ++nt2) {
#pragma unroll
                for (int e = 0; e < 4; ++e) {
                    sv[2 * nt2][e] = 0.f;
                    sv[2 * nt2 + 1][e] = 0.f;
                }
#pragma unroll
                for (int ks = 0; ks < 4; ++ks) {
                    const int g = lane >> 3, r8 = lane & 7;
                    const int nrow = nt2 * 16 + (g >> 1) * 8 + r8;
                    const int ncol = ks * 16 + (g & 1) * 8;
                    const uint32_t off = (uint32_t)(nrow * APAD + ncol) * 2;
                    uint32_t kbh[4], kbl[4];
                    ldmx4(kbh, sb + off);
                    ldmx4(kbl, sb + ATILE * 2 + off);
                    mma_bf16(sv[2 * nt2],     qh[ks], &kbh[0]);
                    mma_bf16(sv[2 * nt2],     qh[ks], &kbl[0]);
                    mma_bf16(sv[2 * nt2],     ql[ks], &kbh[0]);
                    mma_bf16(sv[2 * nt2 + 1], qh[ks], &kbh[2]);
                    mma_bf16(sv[2 * nt2 + 1], qh[ks], &kbl[2]);
                    mma_bf16(sv[2 * nt2 + 1], ql[ks], &kbh[2]);
                }
            }

            // ---- online softmax update ----
            float cm0 = -1e30f, cm1 = -1e30f;
#pragma unroll
            for (int nt = 0; nt < 16; ++nt) {
                cm0 = fmaxf(cm0, fmaxf(sv[nt][0], sv[nt][1]));
                cm1 = fmaxf(cm1, fmaxf(sv[nt][2], sv[nt][3]));
            }
            cm0 = fmaxf(cm0, __shfl_xor_sync(0xffffffffu, cm0, 1));
            cm0 = fmaxf(cm0, __shfl_xor_sync(0xffffffffu, cm0, 2));
            cm1 = fmaxf(cm1, __shfl_xor_sync(0xffffffffu, cm1, 1));
            cm1 = fmaxf(cm1, __shfl_xor_sync(0xffffffffu, cm1, 2));
            const float nm0 = fmaxf(m0, cm0), nm1 = fmaxf(m1, cm1);
            const float rs0 = exp2f(m0 - nm0), rs1 = exp2f(m1 - nm1);
            sum0 *= rs0; sum1 *= rs1;
#pragma unroll
            for (int j = 0; j < 8; ++j) {
                o[j][0] *= rs0; o[j][1] *= rs0;
                o[j][2] *= rs1; o[j][3] *= rs1;
            }
            m0 = nm0; m1 = nm1;

            // ---- P = exp2(S - m), split, PV ----
#pragma unroll
            for (int ks2 = 0; ks2 < 8; ++ks2) {
                const int ntE = 2 * ks2, ntO = 2 * ks2 + 1;
                float p00 = exp2f(sv[ntE][0] - nm0), p01 = exp2f(sv[ntE][1] - nm0);
                float p02 = exp2f(sv[ntE][2] - nm1), p03 = exp2f(sv[ntE][3] - nm1);
                float p10 = exp2f(sv[ntO][0] - nm0), p11 = exp2f(sv[ntO][1] - nm0);
                float p12 = exp2f(sv[ntO][2] - nm1), p13 = exp2f(sv[ntO][3] - nm1);
                sum0 += (p00 + p01) + (p10 + p11);
                sum1 += (p02 + p03) + (p12 + p13);
                uint32_t ph[4], pl[4];
                ph[0] = cvt2bf(p00, p01);
                ph[1] = cvt2bf(p02, p03);
                ph[2] = cvt2bf(p10, p11);
                ph[3] = cvt2bf(p12, p13);
                pl[0] = cvt2bf(p00 - bflo(ph[0]), p01 - bfhi(ph[0]));
                pl[1] = cvt2bf(p02 - bflo(ph[1]), p03 - bfhi(ph[1]));
                pl[2] = cvt2bf(p10 - bflo(ph[2]), p11 - bfhi(ph[2]));
                pl[3] = cvt2bf(p12 - bflo(ph[3]), p13 - bfhi(ph[3]));

#pragma unroll
                for (int ntv = 0; ntv < 4; ++ntv) {
                    const int g = lane >> 3, r8 = lane & 7;
                    const int krow = ks2 * 16 + (g & 1) * 8 + r8;
                    const int vcol = ntv * 16 + (g >> 1) * 8;
                    const uint32_t off = (uint32_t)(krow * APAD + vcol) * 2;
                    uint32_t vbh[4], vbl[4];
                    ldmx4t(vbh, sb + ATILE * 4 + off);
                    ldmx4t(vbl, sb + ATILE * 6 + off);
                    mma_bf16(o[2 * ntv],     ph, &vbh[0]);
                    mma_bf16(o[2 * ntv],     ph, &vbl[0]);
                    mma_bf16(o[2 * ntv],     pl, &vbh[0]);
                    mma_bf16(o[2 * ntv + 1], ph, &vbh[2]);
                    mma_bf16(o[2 * ntv + 1], ph, &vbl[2]);
                    mma_bf16(o[2 * ntv + 1], pl, &vbh[2]);
                }
            }
        }

        // ---- finalize layer: row sums, weight, accumulate into Cc ----
        sum0 += __shfl_xor_sync(0xffffffffu, sum0, 1);
        sum0 += __shfl_xor_sync(0xffffffffu, sum0, 2);
        sum1 += __shfl_xor_sync(0xffffffffu, sum1, 1);
        sum1 += __shfl_xor_sync(0xffffffffu, sum1, 2);
        const float w0 = lw[l] / sum0, w1 = lw[l] / sum1;

        const int g0 = qbase + wq + r;
        float* cp0 = Cc + (size_t)g0 * ROWS + bh * HD;
        float* cp1 = Cc + (size_t)(g0 + 8) * ROWS + bh * HD;
        if (l == 0) {
#pragma unroll
            for (int j = 0; j < 8; ++j) {
                *(float2*)(cp0 + j * 8 + c) = make_float2(w0 * o[j][0], w0 * o[j][1]);
                *(float2*)(cp1 + j * 8 + c) = make_float2(w1 * o[j][2], w1 * o[j][3]);
            }
        } else {
#pragma unroll
            for (int j = 0; j < 8; ++j) {
                float2 a = *(float2*)(cp0 + j * 8 + c);
                float2 b = *(float2*)(cp1 + j * 8 + c);
                a.x += w0 * o[j][0]; a.y += w0 * o[j][1];
                b.x += w1 * o[j][2]; b.y += w1 * o[j][3];
                *(float2*)(cp0 + j * 8 + c) = a;
                *(float2*)(cp1 + j * 8 + c) = b;
            }
        }
    }
}

// ---------------------------------------------------------------------------
extern "C" void kernel_launch(void* const* d_in, const int* in_sizes, int n_in,
                              void* d_out, int out_size) {
    const float* x  = (const float*)d_in[0];
    const float* lo = (const float*)d_in[1];
    const float* Wq = (const float*)d_in[2];
    const float* bq = (const float*)d_in[3];
    const float* Wk = (const float*)d_in[4];
    const float* bk = (const float*)d_in[5];
    const float* Wv = (const float*)d_in[6];
    const float* bv = (const float*)d_in[7];
    const float* Wo = (const float*)d_in[8];
    const float* bo = (const float*)d_in[9];
    const float* lw = (const float*)d_in[10];
    float* out = (float*)d_out;

    float *Qp, *Kp, *Vp, *Cp;
    cudaGetSymbolAddress((void**)&Qp, g_Q);
    cudaGetSymbolAddress((void**)&Kp, g_K);
    cudaGetSymbolAddress((void**)&Vp, g_V);
    cudaGetSymbolAddress((void**)&Cp, g_C);

    cudaFuncSetAttribute(gemm_mma, cudaFuncAttributeMaxDynamicSharedMemorySize,
                         GEMM_SMEM);
    cudaFuncSetAttribute(attn_mma, cudaFuncAttributeMaxDynamicSharedMemorySize,
                         ATTN_SMEM);

    // 1) x -> Q, K[0], V[0]
    {
        GemmOuts o;
        o.W[0] = Wq; o.bias[0] = bq; o.C[0] = Qp;
        o.W[1] = Wk; o.bias[1] = bk; o.C[1] = Kp;
        o.W[2] = Wv; o.bias[2] = bv; o.C[2] = Vp;
        gemm_mma<<<dim3(8, M_X / 128, 3), 256, GEMM_SMEM>>>(x, o);
    }
    // 2) layer_outputs -> K[1..3], V[1..3]
    {
        GemmOuts o;
        o.W[0] = Wk; o.bias[0] = bk; o.C[0] = Kp + (size_t)M_X * D_DIM;
        o.W[1] = Wv; o.bias[1] = bv; o.C[1] = Vp + (size_t)M_X * D_DIM;
        o.W[2] = Wk; o.bias[2] = bk; o.C[2] = Kp + (size_t)M_X * D_DIM;
        gemm_mma<<<dim3(8, M_LO / 128, 2), 256, GEMM_SMEM>>>(lo, o);
    }
    // 3) attention -> combined
    attn_mma<<<dim3(BHD, 8), 256, ATTN_SMEM>>>(Qp, Kp, Vp, lw, Cp);
    // 4) combined @ Wo^T + bo -> out
    {
        GemmOuts o;
        o.W[0] = Wo; o.bias[0] = bo; o.C[0] = out;
        o.W[1] = Wo; o.bias[1] = bo; o.C[1] = out;
        o.W[2] = Wo; o.bias[2] = bo; o.C[2] = out;
        gemm_mma<<<dim3(8, M_X / 128, 1), 256, GEMM_SMEM>>>(Cp, o);
    }
}